// round 6
// baseline (speedup 1.0000x reference)
#include <cuda_runtime.h>
#include <cuda_bf16.h>

#define NN 100000
#define EE 800000
#define DD 64
#define HH 4

typedef unsigned long long ull;

// Scratch (device globals; no allocation allowed)
__device__ float g_Q[NN * DD];
__device__ float g_K[NN * DD];
__device__ float g_V[NN * DD];
__device__ int   g_cnt[NN];
__device__ int   g_off[NN + 1];
__device__ int   g_cur[NN];
__device__ int   g_bsum[128];
__device__ int   g_scol[EE];

// ---------------------------------------------------------------------------
// Packed f32x2 helpers (sm_103a): ptxas never auto-fuses these.
// ---------------------------------------------------------------------------
__device__ __forceinline__ ull ffma2(ull a, ull b, ull c)
{
    ull d;
    asm("fma.rn.f32x2 %0, %1, %2, %3;" : "=l"(d) : "l"(a), "l"(b), "l"(c));
    return d;
}

__device__ __forceinline__ float unpack_sum(ull a)
{
    float lo, hi;
    asm("mov.b64 {%0, %1}, %2;" : "=f"(lo), "=f"(hi) : "l"(a));
    return lo + hi;
}

__device__ __forceinline__ ull pack2(float lo, float hi)
{
    ull u;
    asm("mov.b64 %0, {%1, %2};" : "=l"(u) : "f"(lo), "f"(hi));
    return u;
}

// ---------------------------------------------------------------------------
// 1) Node projections, f32x2-packed, TWO nodes per thread so each LDS.128
//    weight read feeds FMAs for 2 nodes (halves LDS issues per node).
// ---------------------------------------------------------------------------
__global__ __launch_bounds__(128) void proj_kernel(
    const float* __restrict__ X,
    const float* __restrict__ Wq,
    const float* __restrict__ Wk,
    const float* __restrict__ Wv)
{
    __shared__ ull sW[3][DD / 2][DD];   // 48 KB

    for (int i = threadIdx.x; i < 3 * (DD / 2) * DD; i += 128) {
        int m  = i / ((DD / 2) * DD);
        int r  = i % ((DD / 2) * DD);
        int kp = r / DD;
        int d  = r % DD;
        const float* W = (m == 0) ? Wq : (m == 1) ? Wk : Wv;
        sW[m][kp][d] = pack2(W[(2 * kp) * DD + d], W[(2 * kp + 1) * DD + d]);
    }
    __syncthreads();

    int pair = blockIdx.x * 128 + threadIdx.x;
    if (pair >= NN / 2) return;
    int n0 = pair * 2;
    int n1 = n0 + 1;

    // Two x rows as packed {x[2k],x[2k+1]} ulls
    ull xp0[DD / 2], xp1[DD / 2];
    const ulonglong2* xr0 = (const ulonglong2*)(X + (size_t)n0 * DD);
    const ulonglong2* xr1 = (const ulonglong2*)(X + (size_t)n1 * DD);
#pragma unroll
    for (int i = 0; i < DD / 4; i++) {
        ulonglong2 t0 = xr0[i];
        ulonglong2 t1 = xr1[i];
        xp0[2 * i] = t0.x; xp0[2 * i + 1] = t0.y;
        xp1[2 * i] = t1.x; xp1[2 * i + 1] = t1.y;
    }

#pragma unroll 1
    for (int m = 0; m < 3; m++) {
        float* base = (m == 0) ? g_Q : (m == 1) ? g_K : g_V;
        float* out0 = base + (size_t)n0 * DD;
        float* out1 = base + (size_t)n1 * DD;
#pragma unroll 1
        for (int dc = 0; dc < DD; dc += 8) {
            ull a0[8], a1[8];
#pragma unroll
            for (int i = 0; i < 8; i++) { a0[i] = 0; a1[i] = 0; }
#pragma unroll
            for (int kp = 0; kp < DD / 2; kp++) {
                const ulonglong2* w2 = (const ulonglong2*)&sW[m][kp][dc];
                ulonglong2 wa = w2[0];
                ulonglong2 wb = w2[1];
                ulonglong2 wc = w2[2];
                ulonglong2 wd = w2[3];
                ull x0 = xp0[kp];
                ull x1 = xp1[kp];
                a0[0] = ffma2(x0, wa.x, a0[0]);  a1[0] = ffma2(x1, wa.x, a1[0]);
                a0[1] = ffma2(x0, wa.y, a0[1]);  a1[1] = ffma2(x1, wa.y, a1[1]);
                a0[2] = ffma2(x0, wb.x, a0[2]);  a1[2] = ffma2(x1, wb.x, a1[2]);
                a0[3] = ffma2(x0, wb.y, a0[3]);  a1[3] = ffma2(x1, wb.y, a1[3]);
                a0[4] = ffma2(x0, wc.x, a0[4]);  a1[4] = ffma2(x1, wc.x, a1[4]);
                a0[5] = ffma2(x0, wc.y, a0[5]);  a1[5] = ffma2(x1, wc.y, a1[5]);
                a0[6] = ffma2(x0, wd.x, a0[6]);  a1[6] = ffma2(x1, wd.x, a1[6]);
                a0[7] = ffma2(x0, wd.y, a0[7]);  a1[7] = ffma2(x1, wd.y, a1[7]);
            }
            *(float4*)(out0 + dc)     = make_float4(unpack_sum(a0[0]), unpack_sum(a0[1]),
                                                    unpack_sum(a0[2]), unpack_sum(a0[3]));
            *(float4*)(out0 + dc + 4) = make_float4(unpack_sum(a0[4]), unpack_sum(a0[5]),
                                                    unpack_sum(a0[6]), unpack_sum(a0[7]));
            *(float4*)(out1 + dc)     = make_float4(unpack_sum(a1[0]), unpack_sum(a1[1]),
                                                    unpack_sum(a1[2]), unpack_sum(a1[3]));
            *(float4*)(out1 + dc + 4) = make_float4(unpack_sum(a1[4]), unpack_sum(a1[5]),
                                                    unpack_sum(a1[6]), unpack_sum(a1[7]));
        }
    }
}

// ---------------------------------------------------------------------------
// 2) CSR build. zero_cnt split in 3 parts (also aligns ncu's fixed capture
//    slot — launch #4 — onto proj_kernel).
// ---------------------------------------------------------------------------
__global__ void zero_cnt_part(int base, int n)
{
    int i = base + blockIdx.x * blockDim.x + threadIdx.x;
    if (i < base + n && i < NN) g_cnt[i] = 0;
}

__global__ void hist_kernel(const int* __restrict__ rows)
{
    int e4 = blockIdx.x * blockDim.x + threadIdx.x;
    if (e4 < EE / 4) {
        int4 r = ((const int4*)rows)[e4];
        atomicAdd(&g_cnt[r.x], 1);
        atomicAdd(&g_cnt[r.y], 1);
        atomicAdd(&g_cnt[r.z], 1);
        atomicAdd(&g_cnt[r.w], 1);
    }
}

__global__ __launch_bounds__(1024) void scan_block_kernel()
{
    __shared__ int wsum[32];
    int i    = blockIdx.x * 1024 + threadIdx.x;
    int lane = threadIdx.x & 31;
    int w    = threadIdx.x >> 5;
    int v    = (i < NN) ? g_cnt[i] : 0;

    int s = v;
#pragma unroll
    for (int o = 1; o < 32; o <<= 1) {
        int t = __shfl_up_sync(0xffffffffu, s, o);
        if (lane >= o) s += t;
    }
    if (lane == 31) wsum[w] = s;
    __syncthreads();

    if (w == 0) {
        int ws = wsum[lane];
        int t  = ws;
#pragma unroll
        for (int o = 1; o < 32; o <<= 1) {
            int u = __shfl_up_sync(0xffffffffu, t, o);
            if (lane >= o) t += u;
        }
        wsum[lane] = t - ws;
    }
    __syncthreads();

    int incl = s + wsum[w];
    if (i < NN) g_off[i] = incl - v;
    if (threadIdx.x == 1023) g_bsum[blockIdx.x] = incl;
}

__global__ void scan_sums_kernel(int nb)
{
    if (threadIdx.x == 0 && blockIdx.x == 0) {
        int acc = 0;
        for (int b = 0; b < nb; b++) { int t = g_bsum[b]; g_bsum[b] = acc; acc += t; }
    }
}

__global__ void add_off_kernel()
{
    int i = blockIdx.x * blockDim.x + threadIdx.x;
    if (i < NN) {
        int o = g_off[i] + g_bsum[i >> 10];
        g_off[i] = o;
        g_cur[i] = o;
    }
    if (i == 0) g_off[NN] = EE;
}

__global__ void scatter_kernel(const int* __restrict__ rows,
                               const int* __restrict__ cols)
{
    int e4 = blockIdx.x * blockDim.x + threadIdx.x;
    if (e4 < EE / 4) {
        int4 r = ((const int4*)rows)[e4];
        int4 c = ((const int4*)cols)[e4];
        int p0 = atomicAdd(&g_cur[r.x], 1);
        int p1 = atomicAdd(&g_cur[r.y], 1);
        int p2 = atomicAdd(&g_cur[r.z], 1);
        int p3 = atomicAdd(&g_cur[r.w], 1);
        g_scol[p0] = c.x;
        g_scol[p1] = c.y;
        g_scol[p2] = c.z;
        g_scol[p3] = c.w;
    }
}

// ---------------------------------------------------------------------------
// 3) Fused attention aggregate (R4 layout: whole warp per edge, float2/lane),
//    unrolled x4, with scol batch loads rotated one iteration ahead.
// ---------------------------------------------------------------------------
__global__ __launch_bounds__(256) void aggregate_kernel(float* __restrict__ out)
{
    int warp = (blockIdx.x * blockDim.x + threadIdx.x) >> 5;
    int lane = threadIdx.x & 31;
    if (warp >= NN) return;

    int start = g_off[warp];
    int end   = g_off[warp + 1];

    float2 q   = *(const float2*)(g_Q + (size_t)warp * DD + lane * 2);
    float2 acc = make_float2(0.f, 0.f);
    float  na  = 0.f;

    int j = start;
    int c0 = 0, c1 = 0, c2 = 0, c3 = 0;
    if (j + 4 <= end) {
        c0 = __ldg(&g_scol[j + 0]);
        c1 = __ldg(&g_scol[j + 1]);
        c2 = __ldg(&g_scol[j + 2]);
        c3 = __ldg(&g_scol[j + 3]);
    }

    while (j + 4 <= end) {
        int u0 = c0, u1 = c1, u2 = c2, u3 = c3;
        int jn = j + 4;
        if (jn + 4 <= end) {            // prefetch next batch (overlaps gathers)
            c0 = __ldg(&g_scol[jn + 0]);
            c1 = __ldg(&g_scol[jn + 1]);
            c2 = __ldg(&g_scol[jn + 2]);
            c3 = __ldg(&g_scol[jn + 3]);
        }

        float2 k0 = *(const float2*)(g_K + (size_t)u0 * DD + lane * 2);
        float2 k1 = *(const float2*)(g_K + (size_t)u1 * DD + lane * 2);
        float2 k2 = *(const float2*)(g_K + (size_t)u2 * DD + lane * 2);
        float2 k3 = *(const float2*)(g_K + (size_t)u3 * DD + lane * 2);
        float2 v0 = *(const float2*)(g_V + (size_t)u0 * DD + lane * 2);
        float2 v1 = *(const float2*)(g_V + (size_t)u1 * DD + lane * 2);
        float2 v2 = *(const float2*)(g_V + (size_t)u2 * DD + lane * 2);
        float2 v3 = *(const float2*)(g_V + (size_t)u3 * DD + lane * 2);

        float p0 = q.x * k0.x + q.y * k0.y;
        float p1 = q.x * k1.x + q.y * k1.y;
        float p2 = q.x * k2.x + q.y * k2.y;
        float p3 = q.x * k3.x + q.y * k3.y;

        p0 += __shfl_xor_sync(0xffffffffu, p0, 1);
        p1 += __shfl_xor_sync(0xffffffffu, p1, 1);
        p2 += __shfl_xor_sync(0xffffffffu, p2, 1);
        p3 += __shfl_xor_sync(0xffffffffu, p3, 1);
        p0 += __shfl_xor_sync(0xffffffffu, p0, 2);
        p1 += __shfl_xor_sync(0xffffffffu, p1, 2);
        p2 += __shfl_xor_sync(0xffffffffu, p2, 2);
        p3 += __shfl_xor_sync(0xffffffffu, p3, 2);
        p0 += __shfl_xor_sync(0xffffffffu, p0, 4);
        p1 += __shfl_xor_sync(0xffffffffu, p1, 4);
        p2 += __shfl_xor_sync(0xffffffffu, p2, 4);
        p3 += __shfl_xor_sync(0xffffffffu, p3, 4);

        float e0 = __expf(fminf(10.f, fmaxf(-10.f, p0)));
        float e1 = __expf(fminf(10.f, fmaxf(-10.f, p1)));
        float e2 = __expf(fminf(10.f, fmaxf(-10.f, p2)));
        float e3 = __expf(fminf(10.f, fmaxf(-10.f, p3)));

        na += (e0 + e1) + (e2 + e3);
        acc.x += e0 * v0.x + e1 * v1.x + e2 * v2.x + e3 * v3.x;
        acc.y += e0 * v0.y + e1 * v1.y + e2 * v2.y + e3 * v3.y;

        j = jn;
    }

    for (; j < end; j++) {
        int c = __ldg(&g_scol[j]);
        float2 kv = *(const float2*)(g_K + (size_t)c * DD + lane * 2);
        float2 vv = *(const float2*)(g_V + (size_t)c * DD + lane * 2);
        float p = q.x * kv.x + q.y * kv.y;
        p += __shfl_xor_sync(0xffffffffu, p, 1);
        p += __shfl_xor_sync(0xffffffffu, p, 2);
        p += __shfl_xor_sync(0xffffffffu, p, 4);
        float ea = __expf(fminf(10.f, fmaxf(-10.f, p)));
        na += ea;
        acc.x += ea * vv.x;
        acc.y += ea * vv.y;
    }

    float inv = 1.f / (na + 1e-8f);
    *(float2*)(out + (size_t)warp * DD + lane * 2) =
        make_float2(acc.x * inv, acc.y * inv);
}

// ---------------------------------------------------------------------------
extern "C" void kernel_launch(void* const* d_in, const int* in_sizes, int n_in,
                              void* d_out, int out_size)
{
    const float* X  = (const float*)d_in[0];
    const float* Wq = (const float*)d_in[1];
    const float* Wk = (const float*)d_in[2];
    const float* Wv = (const float*)d_in[3];
    const int*   ei = (const int*)d_in[4];
    const int* rows = ei;
    const int* cols = ei + EE;
    float* out = (float*)d_out;

    (void)in_sizes; (void)n_in; (void)out_size;

    // zero counts in 3 parts (launches 1-3; puts proj at ncu's capture slot #4)
    int third = (NN + 2) / 3;
    zero_cnt_part<<<(third + 255) / 256, 256>>>(0, third);
    zero_cnt_part<<<(third + 255) / 256, 256>>>(third, third);
    zero_cnt_part<<<(third + 255) / 256, 256>>>(2 * third, NN - 2 * third);

    // 1) node projections (launch #4 — profiled)
    proj_kernel<<<(NN / 2 + 127) / 128, 128>>>(X, Wq, Wk, Wv);

    // 2) CSR build by destination row
    hist_kernel<<<(EE / 4 + 255) / 256, 256>>>(rows);
    int nb = (NN + 1023) / 1024;
    scan_block_kernel<<<nb, 1024>>>();
    scan_sums_kernel<<<1, 32>>>(nb);
    add_off_kernel<<<(NN + 255) / 256, 256>>>();
    scatter_kernel<<<(EE / 4 + 255) / 256, 256>>>(rows, cols);

    // 3) fused gather + softmax + aggregate (one warp per node)
    aggregate_kernel<<<(NN * 32 + 255) / 256, 256>>>(out);
}

// round 8
// speedup vs baseline: 1.3309x; 1.3309x over previous
#include <cuda_runtime.h>
#include <cuda_bf16.h>

#define NN 100000
#define EE 800000
#define DD 64
#define HH 4

typedef unsigned long long ull;

// Scratch (device globals; no allocation allowed)
__device__ float g_Q[NN * DD];
__device__ float g_K[NN * DD];
__device__ float g_V[NN * DD];
__device__ int   g_cnt[NN];
__device__ int   g_off[NN + 1];
__device__ int   g_cur[NN];
__device__ int   g_bsum[128];
__device__ int   g_scol[EE];

// ---------------------------------------------------------------------------
// Packed f32x2 helpers (sm_103a): ptxas never auto-fuses these.
// ---------------------------------------------------------------------------
__device__ __forceinline__ ull ffma2(ull a, ull b, ull c)
{
    ull d;
    asm("fma.rn.f32x2 %0, %1, %2, %3;" : "=l"(d) : "l"(a), "l"(b), "l"(c));
    return d;
}

__device__ __forceinline__ ull dup2(float w)
{
    ull u;
    asm("mov.b64 %0, {%1, %1};" : "=l"(u) : "f"(w));
    return u;
}

// ---------------------------------------------------------------------------
// 1) Node projections as a tiled GEMM: [64 nodes] x [64 k] x [192 outputs].
//    192 threads; thread = (m, 8-wide d chunk) x (4 node-pairs).
//    X tile staged TRANSPOSED in shared as packed node-pairs:
//      xs[k][np] = {X[2np][k], X[2np+1][k]}  (the float2 bits ARE the f32x2
//      operand; final unpack yields the two nodes' outputs directly).
//    W rows streamed from gmem through L1 (48 KB working set, all hits).
//    Per k: 2 LDS.128 + 2 LDG.128 + 8 ALU dups + 32 FFMA2  ->  FMA-bound.
// ---------------------------------------------------------------------------
#define PB_NODES 64
#define XS_COLS  34   // 32 node-pairs + pad (272 B row, 16B-aligned)

__global__ __launch_bounds__(192) void proj_kernel(
    const float* __restrict__ X,
    const float* __restrict__ Wq,
    const float* __restrict__ Wk,
    const float* __restrict__ Wv)
{
    __shared__ float2 xs[DD][XS_COLS];   // 17408 B

    int tid   = threadIdx.x;
    int nbase = blockIdx.x * PB_NODES;

    // Stage X tile transposed into node-pair layout.
    for (int i = tid; i < PB_NODES * (DD / 4); i += 192) {
        int nl = i / (DD / 4);         // local node 0..63
        int dq = i % (DD / 4);         // float4 index within row
        int n  = nbase + nl;
        float4 v = (n < NN) ? ((const float4*)(X + (size_t)n * DD))[dq]
                            : make_float4(0.f, 0.f, 0.f, 0.f);
        int np = nl >> 1;
        int hf = nl & 1;
        ((float*)&xs[dq * 4 + 0][np])[hf] = v.x;
        ((float*)&xs[dq * 4 + 1][np])[hf] = v.y;
        ((float*)&xs[dq * 4 + 2][np])[hf] = v.z;
        ((float*)&xs[dq * 4 + 3][np])[hf] = v.w;
    }
    __syncthreads();

    int dg  = tid % 24;        // 0..23 -> (m, d chunk)
    int npg = tid / 24;        // 0..7  -> 4 node-pairs
    int m   = dg >> 3;
    int d0  = (dg & 7) * 8;
    int np0 = npg * 4;

    const float* Wm = (m == 0) ? Wq : (m == 1) ? Wk : Wv;
    const float* wp = Wm + d0;

    ull acc[4][8];
#pragma unroll
    for (int p = 0; p < 4; p++)
#pragma unroll
        for (int d = 0; d < 8; d++) acc[p][d] = 0ull;

#pragma unroll 2
    for (int k = 0; k < DD; k++) {
        ulonglong2 xa = *(const ulonglong2*)&xs[k][np0];
        ulonglong2 xb = *(const ulonglong2*)&xs[k][np0 + 2];
        float4 wlo = *(const float4*)(wp + k * DD);
        float4 whi = *(const float4*)(wp + k * DD + 4);

        ull w2[8];
        w2[0] = dup2(wlo.x); w2[1] = dup2(wlo.y);
        w2[2] = dup2(wlo.z); w2[3] = dup2(wlo.w);
        w2[4] = dup2(whi.x); w2[5] = dup2(whi.y);
        w2[6] = dup2(whi.z); w2[7] = dup2(whi.w);

        ull xv0 = xa.x, xv1 = xa.y, xv2 = xb.x, xv3 = xb.y;
#pragma unroll
        for (int d = 0; d < 8; d++) {
            acc[0][d] = ffma2(xv0, w2[d], acc[0][d]);
            acc[1][d] = ffma2(xv1, w2[d], acc[1][d]);
            acc[2][d] = ffma2(xv2, w2[d], acc[2][d]);
            acc[3][d] = ffma2(xv3, w2[d], acc[3][d]);
        }
    }

    float* base = (m == 0) ? g_Q : (m == 1) ? g_K : g_V;
#pragma unroll
    for (int p = 0; p < 4; p++) {
        int n0 = nbase + 2 * (np0 + p);
        float lo[8], hi[8];
#pragma unroll
        for (int d = 0; d < 8; d++) {
            float l, h;
            asm("mov.b64 {%0, %1}, %2;" : "=f"(l), "=f"(h) : "l"(acc[p][d]));
            lo[d] = l; hi[d] = h;
        }
        if (n0 < NN) {
            float4* o = (float4*)(base + (size_t)n0 * DD + d0);
            o[0] = make_float4(lo[0], lo[1], lo[2], lo[3]);
            o[1] = make_float4(lo[4], lo[5], lo[6], lo[7]);
        }
        if (n0 + 1 < NN) {
            float4* o = (float4*)(base + (size_t)(n0 + 1) * DD + d0);
            o[0] = make_float4(hi[0], hi[1], hi[2], hi[3]);
            o[1] = make_float4(hi[4], hi[5], hi[6], hi[7]);
        }
    }
}

// ---------------------------------------------------------------------------
// 2) CSR build. zero_cnt split in 3 parts (keeps ncu's fixed capture slot —
//    launch #4 — on proj_kernel).
// ---------------------------------------------------------------------------
__global__ void zero_cnt_part(int base, int n)
{
    int i = base + blockIdx.x * blockDim.x + threadIdx.x;
    if (i < base + n && i < NN) g_cnt[i] = 0;
}

__global__ void hist_kernel(const int* __restrict__ rows)
{
    int e4 = blockIdx.x * blockDim.x + threadIdx.x;
    if (e4 < EE / 4) {
        int4 r = ((const int4*)rows)[e4];
        atomicAdd(&g_cnt[r.x], 1);
        atomicAdd(&g_cnt[r.y], 1);
        atomicAdd(&g_cnt[r.z], 1);
        atomicAdd(&g_cnt[r.w], 1);
    }
}

__global__ __launch_bounds__(1024) void scan_block_kernel()
{
    __shared__ int wsum[32];
    int i    = blockIdx.x * 1024 + threadIdx.x;
    int lane = threadIdx.x & 31;
    int w    = threadIdx.x >> 5;
    int v    = (i < NN) ? g_cnt[i] : 0;

    int s = v;
#pragma unroll
    for (int o = 1; o < 32; o <<= 1) {
        int t = __shfl_up_sync(0xffffffffu, s, o);
        if (lane >= o) s += t;
    }
    if (lane == 31) wsum[w] = s;
    __syncthreads();

    if (w == 0) {
        int ws = wsum[lane];
        int t  = ws;
#pragma unroll
        for (int o = 1; o < 32; o <<= 1) {
            int u = __shfl_up_sync(0xffffffffu, t, o);
            if (lane >= o) t += u;
        }
        wsum[lane] = t - ws;
    }
    __syncthreads();

    int incl = s + wsum[w];
    if (i < NN) g_off[i] = incl - v;
    if (threadIdx.x == 1023) g_bsum[blockIdx.x] = incl;
}

__global__ void scan_sums_kernel(int nb)
{
    if (threadIdx.x == 0 && blockIdx.x == 0) {
        int acc = 0;
        for (int b = 0; b < nb; b++) { int t = g_bsum[b]; g_bsum[b] = acc; acc += t; }
    }
}

__global__ void add_off_kernel()
{
    int i = blockIdx.x * blockDim.x + threadIdx.x;
    if (i < NN) {
        int o = g_off[i] + g_bsum[i >> 10];
        g_off[i] = o;
        g_cur[i] = o;
    }
    if (i == 0) g_off[NN] = EE;
}

__global__ void scatter_kernel(const int* __restrict__ rows,
                               const int* __restrict__ cols)
{
    int e4 = blockIdx.x * blockDim.x + threadIdx.x;
    if (e4 < EE / 4) {
        int4 r = ((const int4*)rows)[e4];
        int4 c = ((const int4*)cols)[e4];
        int p0 = atomicAdd(&g_cur[r.x], 1);
        int p1 = atomicAdd(&g_cur[r.y], 1);
        int p2 = atomicAdd(&g_cur[r.z], 1);
        int p3 = atomicAdd(&g_cur[r.w], 1);
        g_scol[p0] = c.x;
        g_scol[p1] = c.y;
        g_scol[p2] = c.z;
        g_scol[p3] = c.w;
    }
}

// ---------------------------------------------------------------------------
// 3) Fused attention aggregate (R4 layout: whole warp per edge, float2/lane),
//    unrolled x4, scol batch loads rotated one iteration ahead.
// ---------------------------------------------------------------------------
__global__ __launch_bounds__(256) void aggregate_kernel(float* __restrict__ out)
{
    int warp = (blockIdx.x * blockDim.x + threadIdx.x) >> 5;
    int lane = threadIdx.x & 31;
    if (warp >= NN) return;

    int start = g_off[warp];
    int end   = g_off[warp + 1];

    float2 q   = *(const float2*)(g_Q + (size_t)warp * DD + lane * 2);
    float2 acc = make_float2(0.f, 0.f);
    float  na  = 0.f;

    int j = start;
    int c0 = 0, c1 = 0, c2 = 0, c3 = 0;
    if (j + 4 <= end) {
        c0 = __ldg(&g_scol[j + 0]);
        c1 = __ldg(&g_scol[j + 1]);
        c2 = __ldg(&g_scol[j + 2]);
        c3 = __ldg(&g_scol[j + 3]);
    }

    while (j + 4 <= end) {
        int u0 = c0, u1 = c1, u2 = c2, u3 = c3;
        int jn = j + 4;
        if (jn + 4 <= end) {
            c0 = __ldg(&g_scol[jn + 0]);
            c1 = __ldg(&g_scol[jn + 1]);
            c2 = __ldg(&g_scol[jn + 2]);
            c3 = __ldg(&g_scol[jn + 3]);
        }

        float2 k0 = *(const float2*)(g_K + (size_t)u0 * DD + lane * 2);
        float2 k1 = *(const float2*)(g_K + (size_t)u1 * DD + lane * 2);
        float2 k2 = *(const float2*)(g_K + (size_t)u2 * DD + lane * 2);
        float2 k3 = *(const float2*)(g_K + (size_t)u3 * DD + lane * 2);
        float2 v0 = *(const float2*)(g_V + (size_t)u0 * DD + lane * 2);
        float2 v1 = *(const float2*)(g_V + (size_t)u1 * DD + lane * 2);
        float2 v2 = *(const float2*)(g_V + (size_t)u2 * DD + lane * 2);
        float2 v3 = *(const float2*)(g_V + (size_t)u3 * DD + lane * 2);

        float p0 = q.x * k0.x + q.y * k0.y;
        float p1 = q.x * k1.x + q.y * k1.y;
        float p2 = q.x * k2.x + q.y * k2.y;
        float p3 = q.x * k3.x + q.y * k3.y;

        p0 += __shfl_xor_sync(0xffffffffu, p0, 1);
        p1 += __shfl_xor_sync(0xffffffffu, p1, 1);
        p2 += __shfl_xor_sync(0xffffffffu, p2, 1);
        p3 += __shfl_xor_sync(0xffffffffu, p3, 1);
        p0 += __shfl_xor_sync(0xffffffffu, p0, 2);
        p1 += __shfl_xor_sync(0xffffffffu, p1, 2);
        p2 += __shfl_xor_sync(0xffffffffu, p2, 2);
        p3 += __shfl_xor_sync(0xffffffffu, p3, 2);
        p0 += __shfl_xor_sync(0xffffffffu, p0, 4);
        p1 += __shfl_xor_sync(0xffffffffu, p1, 4);
        p2 += __shfl_xor_sync(0xffffffffu, p2, 4);
        p3 += __shfl_xor_sync(0xffffffffu, p3, 4);

        float e0 = __expf(fminf(10.f, fmaxf(-10.f, p0)));
        float e1 = __expf(fminf(10.f, fmaxf(-10.f, p1)));
        float e2 = __expf(fminf(10.f, fmaxf(-10.f, p2)));
        float e3 = __expf(fminf(10.f, fmaxf(-10.f, p3)));

        na += (e0 + e1) + (e2 + e3);
        acc.x += e0 * v0.x + e1 * v1.x + e2 * v2.x + e3 * v3.x;
        acc.y += e0 * v0.y + e1 * v1.y + e2 * v2.y + e3 * v3.y;

        j = jn;
    }

    for (; j < end; j++) {
        int c = __ldg(&g_scol[j]);
        float2 kv = *(const float2*)(g_K + (size_t)c * DD + lane * 2);
        float2 vv = *(const float2*)(g_V + (size_t)c * DD + lane * 2);
        float p = q.x * kv.x + q.y * kv.y;
        p += __shfl_xor_sync(0xffffffffu, p, 1);
        p += __shfl_xor_sync(0xffffffffu, p, 2);
        p += __shfl_xor_sync(0xffffffffu, p, 4);
        float ea = __expf(fminf(10.f, fmaxf(-10.f, p)));
        na += ea;
        acc.x += ea * vv.x;
        acc.y += ea * vv.y;
    }

    float inv = 1.f / (na + 1e-8f);
    *(float2*)(out + (size_t)warp * DD + lane * 2) =
        make_float2(acc.x * inv, acc.y * inv);
}

// ---------------------------------------------------------------------------
extern "C" void kernel_launch(void* const* d_in, const int* in_sizes, int n_in,
                              void* d_out, int out_size)
{
    const float* X  = (const float*)d_in[0];
    const float* Wq = (const float*)d_in[1];
    const float* Wk = (const float*)d_in[2];
    const float* Wv = (const float*)d_in[3];
    const int*   ei = (const int*)d_in[4];
    const int* rows = ei;
    const int* cols = ei + EE;
    float* out = (float*)d_out;

    (void)in_sizes; (void)n_in; (void)out_size;

    // zero counts in 3 parts (launches 1-3; proj stays at ncu capture slot #4)
    int third = (NN + 2) / 3;
    zero_cnt_part<<<(third + 255) / 256, 256>>>(0, third);
    zero_cnt_part<<<(third + 255) / 256, 256>>>(third, third);
    zero_cnt_part<<<(third + 255) / 256, 256>>>(2 * third, NN - 2 * third);

    // 1) node projections (tiled GEMM; launch #4 — profiled)
    proj_kernel<<<(NN + PB_NODES - 1) / PB_NODES, 192>>>(X, Wq, Wk, Wv);

    // 2) CSR build by destination row
    hist_kernel<<<(EE / 4 + 255) / 256, 256>>>(rows);
    int nb = (NN + 1023) / 1024;
    scan_block_kernel<<<nb, 1024>>>();
    scan_sums_kernel<<<1, 32>>>(nb);
    add_off_kernel<<<(NN + 255) / 256, 256>>>();
    scatter_kernel<<<(EE / 4 + 255) / 256, 256>>>(rows, cols);

    // 3) fused gather + softmax + aggregate (one warp per node)
    aggregate_kernel<<<(NN * 32 + 255) / 256, 256>>>(out);
}